// round 1
// baseline (speedup 1.0000x reference)
#include <cuda_runtime.h>
#include <math.h>

// ---------------------------------------------------------------------------
// SegmentedAttention baseline (fp32 everywhere).
// Pipeline: rmsnorm -> SGEMM (x @ Wqkv) -> RoPE+scatter to segmented layout ->
//           flash-style segment attention with persistent-memory KV prefix ->
//           SGEMM (ao @ Wout) -> d_out.
// ---------------------------------------------------------------------------

#define B_   2
#define N_   8192
#define D_   1024
#define H_   16
#define DH_  64
#define SEG_ 512
#define P_   16
#define NW_  16              // segments per batch (N_/SEG_)
#define ROWS_ (B_ * N_)      // 16384
#define EPS_ 1.1920929e-07f

// Scratch (device globals — allocation-free rule)
__device__ float g_xn [(size_t)ROWS_ * D_];          // 64 MB normalized x
__device__ float g_qkv[(size_t)ROWS_ * 3 * D_];      // 192 MB qkv
__device__ float g_q  [(size_t)32 * H_ * SEG_ * DH_];// 64 MB (scaled by 1/8)
__device__ float g_k  [(size_t)32 * H_ * SEG_ * DH_];
__device__ float g_v  [(size_t)32 * H_ * SEG_ * DH_];
__device__ float g_ao [(size_t)ROWS_ * D_];          // attention out, [row][h*64+d]
__device__ float g_invf[32];

// ---------------------------------------------------------------------------
__global__ void precompute_kernel() {
    int t = threadIdx.x;
    if (t < 32)
        g_invf[t] = (float)(1.0 / pow(10000.0, (double)t / 32.0));
}

// ---------------------------------------------------------------------------
// RMSNorm: one block per row of 1024, 256 threads (float4 each)
__global__ void rmsnorm_kernel(const float* __restrict__ seq,
                               const float* __restrict__ wn) {
    int row = blockIdx.x;
    int t = threadIdx.x;
    const float4* in = reinterpret_cast<const float4*>(seq + (size_t)row * D_);
    float4 x = in[t];
    float ss = x.x * x.x + x.y * x.y + x.z * x.z + x.w * x.w;
    #pragma unroll
    for (int o = 16; o; o >>= 1) ss += __shfl_xor_sync(0xffffffffu, ss, o);
    __shared__ float red[8];
    if ((t & 31) == 0) red[t >> 5] = ss;
    __syncthreads();
    float tot = 0.f;
    #pragma unroll
    for (int iw = 0; iw < 8; iw++) tot += red[iw];
    float r = rsqrtf(tot * (1.0f / 1024.0f) + EPS_);
    float4 wv = reinterpret_cast<const float4*>(wn)[t];
    float4 o;
    o.x = x.x * r * wv.x;
    o.y = x.y * r * wv.y;
    o.z = x.z * r * wv.z;
    o.w = x.w * r * wv.w;
    reinterpret_cast<float4*>(g_xn + (size_t)row * D_)[t] = o;
}

// ---------------------------------------------------------------------------
// Classic 128x128x8 SGEMM, 256 threads, 8x8 per-thread microtile.
// A [M,K] row-major, B [K,N] row-major, C [M,N] row-major.
// M % 128 == 0, N % 128 == 0, K % 8 == 0.
__global__ __launch_bounds__(256)
void sgemm128_kernel(const float* __restrict__ A, const float* __restrict__ B,
                     float* __restrict__ C, int M, int N, int K) {
    __shared__ float As[8][128];
    __shared__ float Bs[8][128];
    int tid = threadIdx.x;
    int tx = tid & 15;   // N dir
    int ty = tid >> 4;   // M dir
    const float* Ab = A + (size_t)blockIdx.y * 128 * K;
    const float* Bb = B + (size_t)blockIdx.x * 128;

    float acc[8][8];
    #pragma unroll
    for (int i = 0; i < 8; i++)
        #pragma unroll
        for (int j = 0; j < 8; j++) acc[i][j] = 0.f;

    int arow = tid >> 1;
    int acol = (tid & 1) * 4;
    int brow = tid >> 5;
    int bcol = (tid & 31) * 4;

    for (int k0 = 0; k0 < K; k0 += 8) {
        float4 a4 = *reinterpret_cast<const float4*>(Ab + (size_t)arow * K + k0 + acol);
        As[acol + 0][arow] = a4.x;
        As[acol + 1][arow] = a4.y;
        As[acol + 2][arow] = a4.z;
        As[acol + 3][arow] = a4.w;
        *reinterpret_cast<float4*>(&Bs[brow][bcol]) =
            *reinterpret_cast<const float4*>(Bb + (size_t)(k0 + brow) * N + bcol);
        __syncthreads();
        #pragma unroll
        for (int kk = 0; kk < 8; kk++) {
            float ar[8], br[8];
            *reinterpret_cast<float4*>(&ar[0]) = *reinterpret_cast<float4*>(&As[kk][ty * 8]);
            *reinterpret_cast<float4*>(&ar[4]) = *reinterpret_cast<float4*>(&As[kk][ty * 8 + 4]);
            *reinterpret_cast<float4*>(&br[0]) = *reinterpret_cast<float4*>(&Bs[kk][tx * 8]);
            *reinterpret_cast<float4*>(&br[4]) = *reinterpret_cast<float4*>(&Bs[kk][tx * 8 + 4]);
            #pragma unroll
            for (int i = 0; i < 8; i++)
                #pragma unroll
                for (int j = 0; j < 8; j++)
                    acc[i][j] = fmaf(ar[i], br[j], acc[i][j]);
        }
        __syncthreads();
    }

    float* Cb = C + (size_t)(blockIdx.y * 128 + ty * 8) * N + blockIdx.x * 128 + tx * 8;
    #pragma unroll
    for (int i = 0; i < 8; i++) {
        *reinterpret_cast<float4*>(&Cb[(size_t)i * N]) =
            make_float4(acc[i][0], acc[i][1], acc[i][2], acc[i][3]);
        *reinterpret_cast<float4*>(&Cb[(size_t)i * N + 4]) =
            make_float4(acc[i][4], acc[i][5], acc[i][6], acc[i][7]);
    }
}

// ---------------------------------------------------------------------------
// RoPE + scatter into segmented [seg][h][s][d] layout. One thread per
// (row, head, pair). Q is pre-scaled by DH^-0.5 = 0.125.
__global__ void rope_split_kernel() {
    int idx = blockIdx.x * blockDim.x + threadIdx.x;
    if (idx >= ROWS_ * H_ * 32) return;
    int t   = idx & 31;
    int h   = (idx >> 5) & 15;
    int row = idx >> 9;             // 0..16383
    int n   = row & (N_ - 1);
    int b   = row >> 13;
    int w   = n >> 9;
    int s   = n & (SEG_ - 1);
    int seg = b * NW_ + w;

    const float* base = g_qkv + (size_t)row * 3072 + h * 64 + 2 * t;
    float q0 = base[0],    q1 = base[1];
    float k0 = base[1024], k1 = base[1025];
    float v0 = base[2048], v1 = base[2049];

    float ang = (float)n * g_invf[t];      // matches reference's fp32 product
    // accurate range reduction in double, then fp32 sincos
    double ad = (double)ang;
    double kq = trunc(ad * 0.15915494309189535);   // 1/(2*pi)
    ad -= kq * 6.283185307179586;
    float sn, cs;
    sincosf((float)ad, &sn, &cs);

    float qo0 = q0 * cs - q1 * sn;
    float qo1 = q1 * cs + q0 * sn;
    float ko0 = k0 * cs - k1 * sn;
    float ko1 = k1 * cs + k0 * sn;

    size_t dst = (((size_t)seg * H_ + h) * SEG_ + s) * DH_ + 2 * t;
    const float SC = 0.125f;  // DH^-0.5 folded into Q
    g_q[dst] = qo0 * SC; g_q[dst + 1] = qo1 * SC;
    g_k[dst] = ko0;      g_k[dst + 1] = ko1;
    g_v[dst] = v0;       g_v[dst + 1] = v1;
}

// ---------------------------------------------------------------------------
// Flash-style segment attention. Block = 256 threads = 64 q-rows x 4 d-splits.
// Chunk 0 = 16 persistent tokens (always visible), chunks 1..16 = 32 seg KV
// rows each, causal (k_idx <= i). Causal chunk skipping per q-tile.
template <int LC>
__device__ __forceinline__ void attn_chunk(
    const float4 q[4], float o[16], float& mrow, float& lsum,
    const float (*Ks)[64], const float (*Vs)[64],
    int c, int i, int kv0, bool is_pm)
{
    float s[LC];
    #pragma unroll
    for (int n = 0; n < LC; n++) {
        const float4* K4 = reinterpret_cast<const float4*>(&Ks[n][c * 16]);
        float4 ka = K4[0], kb = K4[1], kc = K4[2], kd = K4[3];
        float acc = q[0].x * ka.x;
        acc = fmaf(q[0].y, ka.y, acc); acc = fmaf(q[0].z, ka.z, acc); acc = fmaf(q[0].w, ka.w, acc);
        acc = fmaf(q[1].x, kb.x, acc); acc = fmaf(q[1].y, kb.y, acc);
        acc = fmaf(q[1].z, kb.z, acc); acc = fmaf(q[1].w, kb.w, acc);
        acc = fmaf(q[2].x, kc.x, acc); acc = fmaf(q[2].y, kc.y, acc);
        acc = fmaf(q[2].z, kc.z, acc); acc = fmaf(q[2].w, kc.w, acc);
        acc = fmaf(q[3].x, kd.x, acc); acc = fmaf(q[3].y, kd.y, acc);
        acc = fmaf(q[3].z, kd.z, acc); acc = fmaf(q[3].w, kd.w, acc);
        acc += __shfl_xor_sync(0xffffffffu, acc, 1);
        acc += __shfl_xor_sync(0xffffffffu, acc, 2);
        bool vis = is_pm || (kv0 + n <= i);
        s[n] = vis ? acc : -1e30f;
    }
    float mc = mrow;
    #pragma unroll
    for (int n = 0; n < LC; n++) mc = fmaxf(mc, s[n]);
    float corr = __expf(mrow - mc);
    mrow = mc;
    lsum *= corr;
    #pragma unroll
    for (int u = 0; u < 16; u++) o[u] *= corr;
    #pragma unroll
    for (int n = 0; n < LC; n++) {
        float p = __expf(s[n] - mc);
        lsum += p;
        const float4* V4 = reinterpret_cast<const float4*>(&Vs[n][c * 16]);
        float4 va = V4[0], vb = V4[1], vc = V4[2], vd = V4[3];
        o[0]  = fmaf(p, va.x, o[0]);  o[1]  = fmaf(p, va.y, o[1]);
        o[2]  = fmaf(p, va.z, o[2]);  o[3]  = fmaf(p, va.w, o[3]);
        o[4]  = fmaf(p, vb.x, o[4]);  o[5]  = fmaf(p, vb.y, o[5]);
        o[6]  = fmaf(p, vb.z, o[6]);  o[7]  = fmaf(p, vb.w, o[7]);
        o[8]  = fmaf(p, vc.x, o[8]);  o[9]  = fmaf(p, vc.y, o[9]);
        o[10] = fmaf(p, vc.z, o[10]); o[11] = fmaf(p, vc.w, o[11]);
        o[12] = fmaf(p, vd.x, o[12]); o[13] = fmaf(p, vd.y, o[13]);
        o[14] = fmaf(p, vd.z, o[14]); o[15] = fmaf(p, vd.w, o[15]);
    }
}

__global__ __launch_bounds__(256)
void attn_kernel(const float* __restrict__ pm) {
    int qt  = blockIdx.x;   // 0..7   (64-row q tile)
    int h   = blockIdx.y;   // 0..15
    int seg = blockIdx.z;   // 0..31
    int tid = threadIdx.x;
    int r = tid >> 2;       // q row in tile
    int c = tid & 3;        // d split (16 dims each)
    int i = qt * 64 + r;    // q position in segment

    __shared__ float Ks[32][64];
    __shared__ float Vs[32][64];

    const float* qptr = g_q + ((((size_t)seg * H_ + h) * SEG_) + i) * DH_ + c * 16;
    float4 q[4];
    q[0] = *reinterpret_cast<const float4*>(qptr);
    q[1] = *reinterpret_cast<const float4*>(qptr + 4);
    q[2] = *reinterpret_cast<const float4*>(qptr + 8);
    q[3] = *reinterpret_cast<const float4*>(qptr + 12);

    float o[16];
    #pragma unroll
    for (int u = 0; u < 16; u++) o[u] = 0.f;
    float mrow = -1e30f, lsum = 0.f;

    const float* kbase = g_k + (((size_t)seg * H_ + h) * SEG_) * DH_;
    const float* vbase = g_v + (((size_t)seg * H_ + h) * SEG_) * DH_;
    const float* pmk = pm + (size_t)h * P_ * DH_;
    const float* pmv = pm + (size_t)(H_ + h) * P_ * DH_;

    int nch = 2 * qt + 2;   // causal: last chunk needed covers k_idx = i_max

    for (int ch = 0; ch <= nch; ch++) {
        __syncthreads();
        if (ch == 0) {
            if (tid < 128) {
                int f = tid * 8;
                int n = f >> 6, d = f & 63;
                *reinterpret_cast<float4*>(&Ks[n][d])     = *reinterpret_cast<const float4*>(&pmk[n * 64 + d]);
                *reinterpret_cast<float4*>(&Ks[n][d + 4]) = *reinterpret_cast<const float4*>(&pmk[n * 64 + d + 4]);
                *reinterpret_cast<float4*>(&Vs[n][d])     = *reinterpret_cast<const float4*>(&pmv[n * 64 + d]);
                *reinterpret_cast<float4*>(&Vs[n][d + 4]) = *reinterpret_cast<const float4*>(&pmv[n * 64 + d + 4]);
            }
        } else {
            int k0 = (ch - 1) * 32;
            int f = tid * 8;
            int n = f >> 6, d = f & 63;
            const float* ks = kbase + (size_t)(k0 + n) * 64 + d;
            const float* vs = vbase + (size_t)(k0 + n) * 64 + d;
            *reinterpret_cast<float4*>(&Ks[n][d])     = *reinterpret_cast<const float4*>(ks);
            *reinterpret_cast<float4*>(&Ks[n][d + 4]) = *reinterpret_cast<const float4*>(ks + 4);
            *reinterpret_cast<float4*>(&Vs[n][d])     = *reinterpret_cast<const float4*>(vs);
            *reinterpret_cast<float4*>(&Vs[n][d + 4]) = *reinterpret_cast<const float4*>(vs + 4);
        }
        __syncthreads();

        if (ch == 0)
            attn_chunk<16>(q, o, mrow, lsum, Ks, Vs, c, i, 0, true);
        else
            attn_chunk<32>(q, o, mrow, lsum, Ks, Vs, c, i, (ch - 1) * 32, false);
    }

    float inv = 1.f / lsum;
    float* outp = g_ao + (size_t)(seg * SEG_ + i) * D_ + h * DH_ + c * 16;
    #pragma unroll
    for (int u = 0; u < 16; u++) outp[u] = o[u] * inv;
}

// ---------------------------------------------------------------------------
extern "C" void kernel_launch(void* const* d_in, const int* in_sizes, int n_in,
                              void* d_out, int out_size) {
    const float* seq    = (const float*)d_in[0];   // [2,8192,1024]
    const float* w_norm = (const float*)d_in[1];   // [1024]
    const float* Wqkv   = (const float*)d_in[2];   // [1024,3072]
    const float* Wout   = (const float*)d_in[3];   // [1024,1024]
    const float* pm     = (const float*)d_in[4];   // [2,16,16,64]
    float* out = (float*)d_out;                    // [2,8192,1024]

    float* xn  = nullptr; cudaGetSymbolAddress((void**)&xn,  g_xn);
    float* qkv = nullptr; cudaGetSymbolAddress((void**)&qkv, g_qkv);
    float* ao  = nullptr; cudaGetSymbolAddress((void**)&ao,  g_ao);

    precompute_kernel<<<1, 32>>>();
    rmsnorm_kernel<<<ROWS_, 256>>>(seq, w_norm);
    {
        dim3 grid(3072 / 128, ROWS_ / 128);
        sgemm128_kernel<<<grid, 256>>>(xn, Wqkv, qkv, ROWS_, 3072, 1024);
    }
    {
        int total = ROWS_ * H_ * 32;
        rope_split_kernel<<<(total + 255) / 256, 256>>>();
    }
    {
        dim3 grid(8, H_, 32);
        attn_kernel<<<grid, 256>>>(pm);
    }
    {
        dim3 grid(1024 / 128, ROWS_ / 128);
        sgemm128_kernel<<<grid, 256>>>(ao, Wout, out, ROWS_, 1024, 1024);
    }
}

// round 2
// speedup vs baseline: 1.6664x; 1.6664x over previous
#include <cuda_runtime.h>
#include <math.h>
#include <stdint.h>

// ---------------------------------------------------------------------------
// SegmentedAttention round 2: tf32 tensor-core GEMMs (mma.sync.m16n8k8).
// rmsnorm(tf32 out) -> TF32 GEMM (x @ Wqkv) -> RoPE+scatter ->
// flash segment attention (fp32, tf32-rounded out) -> TF32 GEMM (ao @ Wout).
// ---------------------------------------------------------------------------

#define B_   2
#define N_   8192
#define D_   1024
#define H_   16
#define DH_  64
#define SEG_ 512
#define P_   16
#define NW_  16
#define ROWS_ (B_ * N_)      // 16384
#define EPS_ 1.1920929e-07f

__device__ float g_xn [(size_t)ROWS_ * D_];
__device__ float g_qkv[(size_t)ROWS_ * 3 * D_];
__device__ float g_q  [(size_t)32 * H_ * SEG_ * DH_];
__device__ float g_k  [(size_t)32 * H_ * SEG_ * DH_];
__device__ float g_v  [(size_t)32 * H_ * SEG_ * DH_];
__device__ float g_ao [(size_t)ROWS_ * D_];
__device__ float g_wq [(size_t)D_ * 3 * D_];   // tf32-rounded Wqkv
__device__ float g_wo [(size_t)D_ * D_];       // tf32-rounded Wout
__device__ float g_invf[32];

__device__ __forceinline__ float tf32r(float x) {
    uint32_t u;
    asm("cvt.rna.tf32.f32 %0, %1;" : "=r"(u) : "f"(x));
    return __uint_as_float(u);
}

// ---------------------------------------------------------------------------
__global__ void precompute_kernel() {
    int t = threadIdx.x;
    if (t < 32)
        g_invf[t] = (float)(1.0 / pow(10000.0, (double)t / 32.0));
}

__global__ void cvt_tf32_kernel(const float* __restrict__ src,
                                float* __restrict__ dst, int n) {
    int i = blockIdx.x * blockDim.x + threadIdx.x;
    if (i < n) dst[i] = tf32r(src[i]);
}

// ---------------------------------------------------------------------------
__global__ void rmsnorm_kernel(const float* __restrict__ seq,
                               const float* __restrict__ wn) {
    int row = blockIdx.x;
    int t = threadIdx.x;
    const float4* in = reinterpret_cast<const float4*>(seq + (size_t)row * D_);
    float4 x = in[t];
    float ss = x.x * x.x + x.y * x.y + x.z * x.z + x.w * x.w;
    #pragma unroll
    for (int o = 16; o; o >>= 1) ss += __shfl_xor_sync(0xffffffffu, ss, o);
    __shared__ float red[8];
    if ((t & 31) == 0) red[t >> 5] = ss;
    __syncthreads();
    float tot = 0.f;
    #pragma unroll
    for (int iw = 0; iw < 8; iw++) tot += red[iw];
    float r = rsqrtf(tot * (1.0f / 1024.0f) + EPS_);
    float4 wv = reinterpret_cast<const float4*>(wn)[t];
    float4 o;
    o.x = tf32r(x.x * r * wv.x);
    o.y = tf32r(x.y * r * wv.y);
    o.z = tf32r(x.z * r * wv.z);
    o.w = tf32r(x.w * r * wv.w);
    reinterpret_cast<float4*>(g_xn + (size_t)row * D_)[t] = o;
}

// ---------------------------------------------------------------------------
// TF32 tensor-core GEMM: C[M,N] = A[M,K] @ B[K,N], all row-major fp32 holding
// tf32-rounded values. Tile 128x128x16, 256 threads (8 warps, 4x2), warp tile
// 32x64 via mma.sync.m16n8k8.tf32.
#define GA_LD 20    // A smem row stride (16 data + 4 pad) -> ldmatrix conflict-free
#define GB_LD 136   // B smem row stride (128 data + 8 pad) -> LDS conflict-free

__global__ __launch_bounds__(256, 2)
void tf32_gemm_kernel(const float* __restrict__ A, const float* __restrict__ B,
                      float* __restrict__ C, int M, int N, int K) {
    __shared__ float As[2][128][GA_LD];
    __shared__ float Bs[2][16][GB_LD];

    int tid  = threadIdx.x;
    int warp = tid >> 5;
    int lane = tid & 31;
    int wm = warp >> 1;          // 0..3  (M dir, 32 rows each)
    int wn = warp & 1;           // 0..1  (N dir, 64 cols each)
    int g   = lane >> 2;         // groupID
    int tig = lane & 3;          // thread in group

    const float* Ab = A + (size_t)blockIdx.y * 128 * K;
    const float* Bb = B + (size_t)blockIdx.x * 128;

    // ldg assignments
    int av = tid;                // A: 512 float4 / 256 thr = 2 each
    int am0 = av >> 1,        ak0 = (av & 1);        // unused form
    (void)am0; (void)ak0;
    // A: v = tid + i*256 -> m = v>>2 (0..127), kc = v&3
    // B: v = tid + i*256 -> r = v>>5 (0..15),  c4 = v&31

    float acc[2][8][4];
    #pragma unroll
    for (int a = 0; a < 2; a++)
        #pragma unroll
        for (int b = 0; b < 8; b++)
            #pragma unroll
            for (int c = 0; c < 4; c++) acc[a][b][c] = 0.f;

    float4 arg[2], brg[2];

    // prologue: load k0 = 0
    #pragma unroll
    for (int i = 0; i < 2; i++) {
        int v = tid + i * 256;
        arg[i] = *reinterpret_cast<const float4*>(Ab + (size_t)(v >> 2) * K + (v & 3) * 4);
        brg[i] = *reinterpret_cast<const float4*>(Bb + (size_t)(v >> 5) * N + (v & 31) * 4);
    }
    #pragma unroll
    for (int i = 0; i < 2; i++) {
        int v = tid + i * 256;
        *reinterpret_cast<float4*>(&As[0][v >> 2][(v & 3) * 4]) = arg[i];
        *reinterpret_cast<float4*>(&Bs[0][v >> 5][(v & 31) * 4]) = brg[i];
    }
    __syncthreads();

    int cur = 0;
    // per-thread ldmatrix row/segment
    int lrow = lane & 15;
    int lseg = (lane >> 4) * 4;

    for (int k0 = 16; k0 <= K; k0 += 16) {
        bool more = (k0 < K);
        if (more) {
            #pragma unroll
            for (int i = 0; i < 2; i++) {
                int v = tid + i * 256;
                arg[i] = *reinterpret_cast<const float4*>(Ab + (size_t)(v >> 2) * K + k0 + (v & 3) * 4);
                brg[i] = *reinterpret_cast<const float4*>(Bb + (size_t)(k0 + (v >> 5)) * N + (v & 31) * 4);
            }
        }

        // compute stage 'cur': 2 k-steps of 8
        #pragma unroll
        for (int ks = 0; ks < 2; ks++) {
            uint32_t afr[2][4];
            #pragma unroll
            for (int tm = 0; tm < 2; tm++) {
                const float* p = &As[cur][wm * 32 + tm * 16 + lrow][ks * 8 + lseg];
                uint32_t saddr = (uint32_t)__cvta_generic_to_shared(p);
                asm volatile(
                    "ldmatrix.sync.aligned.m8n8.x4.shared.b16 {%0,%1,%2,%3}, [%4];"
                    : "=r"(afr[tm][0]), "=r"(afr[tm][1]), "=r"(afr[tm][2]), "=r"(afr[tm][3])
                    : "r"(saddr));
            }
            uint32_t bfr[8][2];
            #pragma unroll
            for (int j = 0; j < 8; j++) {
                int col = wn * 64 + j * 8 + g;
                bfr[j][0] = __float_as_uint(Bs[cur][ks * 8 + tig][col]);
                bfr[j][1] = __float_as_uint(Bs[cur][ks * 8 + tig + 4][col]);
            }
            #pragma unroll
            for (int tm = 0; tm < 2; tm++)
                #pragma unroll
                for (int j = 0; j < 8; j++) {
                    asm volatile(
                        "mma.sync.aligned.m16n8k8.row.col.f32.tf32.tf32.f32 "
                        "{%0,%1,%2,%3}, {%4,%5,%6,%7}, {%8,%9}, {%0,%1,%2,%3};"
                        : "+f"(acc[tm][j][0]), "+f"(acc[tm][j][1]),
                          "+f"(acc[tm][j][2]), "+f"(acc[tm][j][3])
                        : "r"(afr[tm][0]), "r"(afr[tm][1]), "r"(afr[tm][2]), "r"(afr[tm][3]),
                          "r"(bfr[j][0]), "r"(bfr[j][1]));
                }
        }

        if (more) {
            int nxt = cur ^ 1;
            #pragma unroll
            for (int i = 0; i < 2; i++) {
                int v = tid + i * 256;
                *reinterpret_cast<float4*>(&As[nxt][v >> 2][(v & 3) * 4]) = arg[i];
                *reinterpret_cast<float4*>(&Bs[nxt][v >> 5][(v & 31) * 4]) = brg[i];
            }
            __syncthreads();
            cur = nxt;
        }
    }

    // epilogue
    int rbase = blockIdx.y * 128 + wm * 32;
    int cbase = blockIdx.x * 128 + wn * 64;
    #pragma unroll
    for (int tm = 0; tm < 2; tm++) {
        #pragma unroll
        for (int j = 0; j < 8; j++) {
            int row0 = rbase + tm * 16 + g;
            int col  = cbase + j * 8 + 2 * tig;
            *reinterpret_cast<float2*>(&C[(size_t)row0 * N + col]) =
                make_float2(acc[tm][j][0], acc[tm][j][1]);
            *reinterpret_cast<float2*>(&C[(size_t)(row0 + 8) * N + col]) =
                make_float2(acc[tm][j][2], acc[tm][j][3]);
        }
    }
}

// ---------------------------------------------------------------------------
__global__ void rope_split_kernel() {
    int idx = blockIdx.x * blockDim.x + threadIdx.x;
    if (idx >= ROWS_ * H_ * 32) return;
    int t   = idx & 31;
    int h   = (idx >> 5) & 15;
    int row = idx >> 9;
    int n   = row & (N_ - 1);
    int b   = row >> 13;
    int w   = n >> 9;
    int s   = n & (SEG_ - 1);
    int seg = b * NW_ + w;

    const float* base = g_qkv + (size_t)row * 3072 + h * 64 + 2 * t;
    float q0 = base[0],    q1 = base[1];
    float k0 = base[1024], k1 = base[1025];
    float v0 = base[2048], v1 = base[2049];

    float ang = (float)n * g_invf[t];
    double ad = (double)ang;
    double kq = trunc(ad * 0.15915494309189535);
    ad -= kq * 6.283185307179586;
    float sn, cs;
    sincosf((float)ad, &sn, &cs);

    float qo0 = q0 * cs - q1 * sn;
    float qo1 = q1 * cs + q0 * sn;
    float ko0 = k0 * cs - k1 * sn;
    float ko1 = k1 * cs + k0 * sn;

    size_t dst = (((size_t)seg * H_ + h) * SEG_ + s) * DH_ + 2 * t;
    const float SC = 0.125f;
    g_q[dst] = qo0 * SC; g_q[dst + 1] = qo1 * SC;
    g_k[dst] = ko0;      g_k[dst + 1] = ko1;
    g_v[dst] = v0;       g_v[dst + 1] = v1;
}

// ---------------------------------------------------------------------------
template <int LC>
__device__ __forceinline__ void attn_chunk(
    const float4 q[4], float o[16], float& mrow, float& lsum,
    const float (*Ks)[64], const float (*Vs)[64],
    int c, int i, int kv0, bool is_pm)
{
    float s[LC];
    #pragma unroll
    for (int n = 0; n < LC; n++) {
        const float4* K4 = reinterpret_cast<const float4*>(&Ks[n][c * 16]);
        float4 ka = K4[0], kb = K4[1], kc = K4[2], kd = K4[3];
        float acc = q[0].x * ka.x;
        acc = fmaf(q[0].y, ka.y, acc); acc = fmaf(q[0].z, ka.z, acc); acc = fmaf(q[0].w, ka.w, acc);
        acc = fmaf(q[1].x, kb.x, acc); acc = fmaf(q[1].y, kb.y, acc);
        acc = fmaf(q[1].z, kb.z, acc); acc = fmaf(q[1].w, kb.w, acc);
        acc = fmaf(q[2].x, kc.x, acc); acc = fmaf(q[2].y, kc.y, acc);
        acc = fmaf(q[2].z, kc.z, acc); acc = fmaf(q[2].w, kc.w, acc);
        acc = fmaf(q[3].x, kd.x, acc); acc = fmaf(q[3].y, kd.y, acc);
        acc = fmaf(q[3].z, kd.z, acc); acc = fmaf(q[3].w, kd.w, acc);
        acc += __shfl_xor_sync(0xffffffffu, acc, 1);
        acc += __shfl_xor_sync(0xffffffffu, acc, 2);
        bool vis = is_pm || (kv0 + n <= i);
        s[n] = vis ? acc : -1e30f;
    }
    float mc = mrow;
    #pragma unroll
    for (int n = 0; n < LC; n++) mc = fmaxf(mc, s[n]);
    float corr = __expf(mrow - mc);
    mrow = mc;
    lsum *= corr;
    #pragma unroll
    for (int u = 0; u < 16; u++) o[u] *= corr;
    #pragma unroll
    for (int n = 0; n < LC; n++) {
        float p = __expf(s[n] - mc);
        lsum += p;
        const float4* V4 = reinterpret_cast<const float4*>(&Vs[n][c * 16]);
        float4 va = V4[0], vb = V4[1], vc = V4[2], vd = V4[3];
        o[0]  = fmaf(p, va.x, o[0]);  o[1]  = fmaf(p, va.y, o[1]);
        o[2]  = fmaf(p, va.z, o[2]);  o[3]  = fmaf(p, va.w, o[3]);
        o[4]  = fmaf(p, vb.x, o[4]);  o[5]  = fmaf(p, vb.y, o[5]);
        o[6]  = fmaf(p, vb.z, o[6]);  o[7]  = fmaf(p, vb.w, o[7]);
        o[8]  = fmaf(p, vc.x, o[8]);  o[9]  = fmaf(p, vc.y, o[9]);
        o[10] = fmaf(p, vc.z, o[10]); o[11] = fmaf(p, vc.w, o[11]);
        o[12] = fmaf(p, vd.x, o[12]); o[13] = fmaf(p, vd.y, o[13]);
        o[14] = fmaf(p, vd.z, o[14]); o[15] = fmaf(p, vd.w, o[15]);
    }
}

__global__ __launch_bounds__(256)
void attn_kernel(const float* __restrict__ pm) {
    int qt  = blockIdx.x;
    int h   = blockIdx.y;
    int seg = blockIdx.z;
    int tid = threadIdx.x;
    int r = tid >> 2;
    int c = tid & 3;
    int i = qt * 64 + r;

    __shared__ float Ks[32][64];
    __shared__ float Vs[32][64];

    const float* qptr = g_q + ((((size_t)seg * H_ + h) * SEG_) + i) * DH_ + c * 16;
    float4 q[4];
    q[0] = *reinterpret_cast<const float4*>(qptr);
    q[1] = *reinterpret_cast<const float4*>(qptr + 4);
    q[2] = *reinterpret_cast<const float4*>(qptr + 8);
    q[3] = *reinterpret_cast<const float4*>(qptr + 12);

    float o[16];
    #pragma unroll
    for (int u = 0; u < 16; u++) o[u] = 0.f;
    float mrow = -1e30f, lsum = 0.f;

    const float* kbase = g_k + (((size_t)seg * H_ + h) * SEG_) * DH_;
    const float* vbase = g_v + (((size_t)seg * H_ + h) * SEG_) * DH_;
    const float* pmk = pm + (size_t)h * P_ * DH_;
    const float* pmv = pm + (size_t)(H_ + h) * P_ * DH_;

    int nch = 2 * qt + 2;

    for (int ch = 0; ch <= nch; ch++) {
        __syncthreads();
        if (ch == 0) {
            if (tid < 128) {
                int f = tid * 8;
                int n = f >> 6, d = f & 63;
                *reinterpret_cast<float4*>(&Ks[n][d])     = *reinterpret_cast<const float4*>(&pmk[n * 64 + d]);
                *reinterpret_cast<float4*>(&Ks[n][d + 4]) = *reinterpret_cast<const float4*>(&pmk[n * 64 + d + 4]);
                *reinterpret_cast<float4*>(&Vs[n][d])     = *reinterpret_cast<const float4*>(&pmv[n * 64 + d]);
                *reinterpret_cast<float4*>(&Vs[n][d + 4]) = *reinterpret_cast<const float4*>(&pmv[n * 64 + d + 4]);
            }
        } else {
            int k0 = (ch - 1) * 32;
            int f = tid * 8;
            int n = f >> 6, d = f & 63;
            const float* ks = kbase + (size_t)(k0 + n) * 64 + d;
            const float* vs = vbase + (size_t)(k0 + n) * 64 + d;
            *reinterpret_cast<float4*>(&Ks[n][d])     = *reinterpret_cast<const float4*>(ks);
            *reinterpret_cast<float4*>(&Ks[n][d + 4]) = *reinterpret_cast<const float4*>(ks + 4);
            *reinterpret_cast<float4*>(&Vs[n][d])     = *reinterpret_cast<const float4*>(vs);
            *reinterpret_cast<float4*>(&Vs[n][d + 4]) = *reinterpret_cast<const float4*>(vs + 4);
        }
        __syncthreads();

        if (ch == 0)
            attn_chunk<16>(q, o, mrow, lsum, Ks, Vs, c, i, 0, true);
        else
            attn_chunk<32>(q, o, mrow, lsum, Ks, Vs, c, i, (ch - 1) * 32, false);
    }

    float inv = 1.f / lsum;
    float* outp = g_ao + (size_t)(seg * SEG_ + i) * D_ + h * DH_ + c * 16;
    #pragma unroll
    for (int u = 0; u < 16; u++) outp[u] = tf32r(o[u] * inv);
}

// ---------------------------------------------------------------------------
extern "C" void kernel_launch(void* const* d_in, const int* in_sizes, int n_in,
                              void* d_out, int out_size) {
    const float* seq    = (const float*)d_in[0];
    const float* w_norm = (const float*)d_in[1];
    const float* Wqkv   = (const float*)d_in[2];
    const float* Wout   = (const float*)d_in[3];
    const float* pm     = (const float*)d_in[4];
    float* out = (float*)d_out;

    float* xn  = nullptr; cudaGetSymbolAddress((void**)&xn,  g_xn);
    float* qkv = nullptr; cudaGetSymbolAddress((void**)&qkv, g_qkv);
    float* ao  = nullptr; cudaGetSymbolAddress((void**)&ao,  g_ao);
    float* wq  = nullptr; cudaGetSymbolAddress((void**)&wq,  g_wq);
    float* wo  = nullptr; cudaGetSymbolAddress((void**)&wo,  g_wo);

    precompute_kernel<<<1, 32>>>();
    cvt_tf32_kernel<<<(3 * D_ * D_ + 255) / 256, 256>>>(Wqkv, wq, 3 * D_ * D_);
    cvt_tf32_kernel<<<(D_ * D_ + 255) / 256, 256>>>(Wout, wo, D_ * D_);
    rmsnorm_kernel<<<ROWS_, 256>>>(seq, w_norm);
    {
        dim3 grid(3072 / 128, ROWS_ / 128);
        tf32_gemm_kernel<<<grid, 256>>>(xn, wq, qkv, ROWS_, 3072, 1024);
    }
    {
        int total = ROWS_ * H_ * 32;
        rope_split_kernel<<<(total + 255) / 256, 256>>>();
    }
    {
        dim3 grid(8, H_, 32);
        attn_kernel<<<grid, 256>>>(pm);
    }
    {
        dim3 grid(1024 / 128, ROWS_ / 128);
        tf32_gemm_kernel<<<grid, 256>>>(ao, wo, out, ROWS_, 1024, 1024);
    }
}

// round 3
// speedup vs baseline: 4.6627x; 2.7981x over previous
#include <cuda_runtime.h>
#include <math.h>
#include <stdint.h>

// ---------------------------------------------------------------------------
// SegmentedAttention round 3: tf32 mma.sync for GEMMs AND attention.
// ---------------------------------------------------------------------------

#define B_   2
#define N_   8192
#define D_   1024
#define H_   16
#define DH_  64
#define SEG_ 512
#define P_   16
#define NW_  16
#define ROWS_ (B_ * N_)      // 16384
#define EPS_ 1.1920929e-07f

__device__ float g_xn [(size_t)ROWS_ * D_];
__device__ float g_qkv[(size_t)ROWS_ * 3 * D_];
__device__ float g_q  [(size_t)32 * H_ * SEG_ * DH_];
__device__ float g_k  [(size_t)32 * H_ * SEG_ * DH_];
__device__ float g_v  [(size_t)32 * H_ * SEG_ * DH_];
__device__ float g_ao [(size_t)ROWS_ * D_];
__device__ float g_wq [(size_t)D_ * 3 * D_];
__device__ float g_wo [(size_t)D_ * D_];
__device__ float g_invf[32];

__device__ __forceinline__ float tf32r(float x) {
    uint32_t u;
    asm("cvt.rna.tf32.f32 %0, %1;" : "=r"(u) : "f"(x));
    return __uint_as_float(u);
}

__device__ __forceinline__ void mma_tf32(float* c, const uint32_t* a, const uint32_t* b) {
    asm volatile(
        "mma.sync.aligned.m16n8k8.row.col.f32.tf32.tf32.f32 "
        "{%0,%1,%2,%3}, {%4,%5,%6,%7}, {%8,%9}, {%0,%1,%2,%3};"
        : "+f"(c[0]), "+f"(c[1]), "+f"(c[2]), "+f"(c[3])
        : "r"(a[0]), "r"(a[1]), "r"(a[2]), "r"(a[3]), "r"(b[0]), "r"(b[1]));
}

// ---------------------------------------------------------------------------
__global__ void precompute_kernel() {
    int t = threadIdx.x;
    if (t < 32)
        g_invf[t] = (float)(1.0 / pow(10000.0, (double)t / 32.0));
}

__global__ void cvt_tf32_kernel(const float* __restrict__ src,
                                float* __restrict__ dst, int n) {
    int i = blockIdx.x * blockDim.x + threadIdx.x;
    if (i < n) dst[i] = tf32r(src[i]);
}

// ---------------------------------------------------------------------------
__global__ void rmsnorm_kernel(const float* __restrict__ seq,
                               const float* __restrict__ wn) {
    int row = blockIdx.x;
    int t = threadIdx.x;
    const float4* in = reinterpret_cast<const float4*>(seq + (size_t)row * D_);
    float4 x = in[t];
    float ss = x.x * x.x + x.y * x.y + x.z * x.z + x.w * x.w;
    #pragma unroll
    for (int o = 16; o; o >>= 1) ss += __shfl_xor_sync(0xffffffffu, ss, o);
    __shared__ float red[8];
    if ((t & 31) == 0) red[t >> 5] = ss;
    __syncthreads();
    float tot = 0.f;
    #pragma unroll
    for (int iw = 0; iw < 8; iw++) tot += red[iw];
    float r = rsqrtf(tot * (1.0f / 1024.0f) + EPS_);
    float4 wv = reinterpret_cast<const float4*>(wn)[t];
    float4 o;
    o.x = tf32r(x.x * r * wv.x);
    o.y = tf32r(x.y * r * wv.y);
    o.z = tf32r(x.z * r * wv.z);
    o.w = tf32r(x.w * r * wv.w);
    reinterpret_cast<float4*>(g_xn + (size_t)row * D_)[t] = o;
}

// ---------------------------------------------------------------------------
// TF32 tensor-core GEMM (unchanged from round 2 — proven correct).
#define GA_LD 20
#define GB_LD 136

__global__ __launch_bounds__(256, 2)
void tf32_gemm_kernel(const float* __restrict__ A, const float* __restrict__ B,
                      float* __restrict__ C, int M, int N, int K) {
    __shared__ float As[2][128][GA_LD];
    __shared__ float Bs[2][16][GB_LD];

    int tid  = threadIdx.x;
    int warp = tid >> 5;
    int lane = tid & 31;
    int wm = warp >> 1;
    int wn = warp & 1;
    int g   = lane >> 2;
    int tig = lane & 3;

    const float* Ab = A + (size_t)blockIdx.y * 128 * K;
    const float* Bb = B + (size_t)blockIdx.x * 128;

    float acc[2][8][4];
    #pragma unroll
    for (int a = 0; a < 2; a++)
        #pragma unroll
        for (int b = 0; b < 8; b++)
            #pragma unroll
            for (int c = 0; c < 4; c++) acc[a][b][c] = 0.f;

    float4 arg[2], brg[2];

    #pragma unroll
    for (int i = 0; i < 2; i++) {
        int v = tid + i * 256;
        arg[i] = *reinterpret_cast<const float4*>(Ab + (size_t)(v >> 2) * K + (v & 3) * 4);
        brg[i] = *reinterpret_cast<const float4*>(Bb + (size_t)(v >> 5) * N + (v & 31) * 4);
    }
    #pragma unroll
    for (int i = 0; i < 2; i++) {
        int v = tid + i * 256;
        *reinterpret_cast<float4*>(&As[0][v >> 2][(v & 3) * 4]) = arg[i];
        *reinterpret_cast<float4*>(&Bs[0][v >> 5][(v & 31) * 4]) = brg[i];
    }
    __syncthreads();

    int cur = 0;
    int lrow = lane & 15;
    int lseg = (lane >> 4) * 4;

    for (int k0 = 16; k0 <= K; k0 += 16) {
        bool more = (k0 < K);
        if (more) {
            #pragma unroll
            for (int i = 0; i < 2; i++) {
                int v = tid + i * 256;
                arg[i] = *reinterpret_cast<const float4*>(Ab + (size_t)(v >> 2) * K + k0 + (v & 3) * 4);
                brg[i] = *reinterpret_cast<const float4*>(Bb + (size_t)(k0 + (v >> 5)) * N + (v & 31) * 4);
            }
        }

        #pragma unroll
        for (int ks = 0; ks < 2; ks++) {
            uint32_t afr[2][4];
            #pragma unroll
            for (int tm = 0; tm < 2; tm++) {
                const float* p = &As[cur][wm * 32 + tm * 16 + lrow][ks * 8 + lseg];
                uint32_t saddr = (uint32_t)__cvta_generic_to_shared(p);
                asm volatile(
                    "ldmatrix.sync.aligned.m8n8.x4.shared.b16 {%0,%1,%2,%3}, [%4];"
                    : "=r"(afr[tm][0]), "=r"(afr[tm][1]), "=r"(afr[tm][2]), "=r"(afr[tm][3])
                    : "r"(saddr));
            }
            uint32_t bfr[8][2];
            #pragma unroll
            for (int j = 0; j < 8; j++) {
                int col = wn * 64 + j * 8 + g;
                bfr[j][0] = __float_as_uint(Bs[cur][ks * 8 + tig][col]);
                bfr[j][1] = __float_as_uint(Bs[cur][ks * 8 + tig + 4][col]);
            }
            #pragma unroll
            for (int tm = 0; tm < 2; tm++)
                #pragma unroll
                for (int j = 0; j < 8; j++)
                    mma_tf32(acc[tm][j], afr[tm], bfr[j]);
        }

        if (more) {
            int nxt = cur ^ 1;
            #pragma unroll
            for (int i = 0; i < 2; i++) {
                int v = tid + i * 256;
                *reinterpret_cast<float4*>(&As[nxt][v >> 2][(v & 3) * 4]) = arg[i];
                *reinterpret_cast<float4*>(&Bs[nxt][v >> 5][(v & 31) * 4]) = brg[i];
            }
            __syncthreads();
            cur = nxt;
        }
    }

    int rbase = blockIdx.y * 128 + wm * 32;
    int cbase = blockIdx.x * 128 + wn * 64;
    #pragma unroll
    for (int tm = 0; tm < 2; tm++) {
        #pragma unroll
        for (int j = 0; j < 8; j++) {
            int row0 = rbase + tm * 16 + g;
            int col  = cbase + j * 8 + 2 * tig;
            *reinterpret_cast<float2*>(&C[(size_t)row0 * N + col]) =
                make_float2(acc[tm][j][0], acc[tm][j][1]);
            *reinterpret_cast<float2*>(&C[(size_t)(row0 + 8) * N + col]) =
                make_float2(acc[tm][j][2], acc[tm][j][3]);
        }
    }
}

// ---------------------------------------------------------------------------
__global__ void rope_split_kernel() {
    int idx = blockIdx.x * blockDim.x + threadIdx.x;
    if (idx >= ROWS_ * H_ * 32) return;
    int t   = idx & 31;
    int h   = (idx >> 5) & 15;
    int row = idx >> 9;
    int n   = row & (N_ - 1);
    int b   = row >> 13;
    int w   = n >> 9;
    int s   = n & (SEG_ - 1);
    int seg = b * NW_ + w;

    const float* base = g_qkv + (size_t)row * 3072 + h * 64 + 2 * t;
    float q0 = base[0],    q1 = base[1];
    float k0 = base[1024], k1 = base[1025];
    float v0 = base[2048], v1 = base[2049];

    float ang = (float)n * g_invf[t];
    double ad = (double)ang;
    double kq = trunc(ad * 0.15915494309189535);
    ad -= kq * 6.283185307179586;
    float sn, cs;
    sincosf((float)ad, &sn, &cs);

    float qo0 = q0 * cs - q1 * sn;
    float qo1 = q1 * cs + q0 * sn;
    float ko0 = k0 * cs - k1 * sn;
    float ko1 = k1 * cs + k0 * sn;

    size_t dst = (((size_t)seg * H_ + h) * SEG_ + s) * DH_ + 2 * t;
    const float SC = 0.125f;
    g_q[dst] = tf32r(qo0 * SC); g_q[dst + 1] = tf32r(qo1 * SC);
    g_k[dst] = tf32r(ko0);      g_k[dst + 1] = tf32r(ko1);
    g_v[dst] = tf32r(v0);       g_v[dst + 1] = tf32r(v1);
}

// ---------------------------------------------------------------------------
// Tensor-core flash attention. Block = 128 threads = 4 warps; each warp owns
// 16 q rows of a 64-row q tile. K/V chunks of 32 (pm chunk = 16) staged in
// S[] (K rows 0..31, V rows 32..63, 72-float padded rows -> conflict-free
// scalar LDS for mma B fragments). P re-laid out via warp-private smem.
#define KP_ 72
#define PP_ 40

template<int NJ, bool PM>
__device__ __forceinline__ void attn_step(
    const float (*S)[KP_], float (*Psw)[PP_],
    const uint32_t qf[8][4], float o[8][4],
    float& m0, float& m1, float& l0, float& l1,
    int kv0, int i0, int i1, int g, int tig)
{
    float s[NJ][4];
    #pragma unroll
    for (int j = 0; j < NJ; j++)
        s[j][0] = s[j][1] = s[j][2] = s[j][3] = 0.f;

    #pragma unroll
    for (int ks = 0; ks < 8; ks++) {
        uint32_t b[NJ][2];
        #pragma unroll
        for (int j = 0; j < NJ; j++) {
            b[j][0] = __float_as_uint(S[j * 8 + g][ks * 8 + tig]);
            b[j][1] = __float_as_uint(S[j * 8 + g][ks * 8 + tig + 4]);
        }
        #pragma unroll
        for (int j = 0; j < NJ; j++)
            mma_tf32(s[j], qf[ks], b[j]);
    }

    if (!PM) {
        #pragma unroll
        for (int j = 0; j < NJ; j++) {
            int c0 = kv0 + j * 8 + 2 * tig;
            if (c0     > i0) s[j][0] = -1e30f;
            if (c0 + 1 > i0) s[j][1] = -1e30f;
            if (c0     > i1) s[j][2] = -1e30f;
            if (c0 + 1 > i1) s[j][3] = -1e30f;
        }
    }

    float cm0 = -1e30f, cm1 = -1e30f;
    #pragma unroll
    for (int j = 0; j < NJ; j++) {
        cm0 = fmaxf(cm0, fmaxf(s[j][0], s[j][1]));
        cm1 = fmaxf(cm1, fmaxf(s[j][2], s[j][3]));
    }
    cm0 = fmaxf(cm0, __shfl_xor_sync(0xffffffffu, cm0, 1));
    cm0 = fmaxf(cm0, __shfl_xor_sync(0xffffffffu, cm0, 2));
    cm1 = fmaxf(cm1, __shfl_xor_sync(0xffffffffu, cm1, 1));
    cm1 = fmaxf(cm1, __shfl_xor_sync(0xffffffffu, cm1, 2));

    float m0n = fmaxf(m0, cm0), m1n = fmaxf(m1, cm1);
    float cr0 = __expf(m0 - m0n), cr1 = __expf(m1 - m1n);
    m0 = m0n; m1 = m1n;

    float ps0 = 0.f, ps1 = 0.f;
    #pragma unroll
    for (int j = 0; j < NJ; j++) {
        float p0 = __expf(s[j][0] - m0n);
        float p1 = __expf(s[j][1] - m0n);
        float p2 = __expf(s[j][2] - m1n);
        float p3 = __expf(s[j][3] - m1n);
        ps0 += p0 + p1;
        ps1 += p2 + p3;
        *reinterpret_cast<float2*>(&Psw[g][j * 8 + 2 * tig])     = make_float2(p0, p1);
        *reinterpret_cast<float2*>(&Psw[g + 8][j * 8 + 2 * tig]) = make_float2(p2, p3);
    }
    ps0 += __shfl_xor_sync(0xffffffffu, ps0, 1);
    ps0 += __shfl_xor_sync(0xffffffffu, ps0, 2);
    ps1 += __shfl_xor_sync(0xffffffffu, ps1, 1);
    ps1 += __shfl_xor_sync(0xffffffffu, ps1, 2);
    l0 = l0 * cr0 + ps0;
    l1 = l1 * cr1 + ps1;

    #pragma unroll
    for (int j = 0; j < 8; j++) {
        o[j][0] *= cr0; o[j][1] *= cr0;
        o[j][2] *= cr1; o[j][3] *= cr1;
    }

    __syncwarp();
    #pragma unroll
    for (int ks2 = 0; ks2 < NJ; ks2++) {
        uint32_t a[4];
        a[0] = __float_as_uint(Psw[g][ks2 * 8 + tig]);
        a[1] = __float_as_uint(Psw[g + 8][ks2 * 8 + tig]);
        a[2] = __float_as_uint(Psw[g][ks2 * 8 + tig + 4]);
        a[3] = __float_as_uint(Psw[g + 8][ks2 * 8 + tig + 4]);
        #pragma unroll
        for (int j = 0; j < 8; j++) {
            uint32_t b[2];
            b[0] = __float_as_uint(S[32 + ks2 * 8 + tig][j * 8 + g]);
            b[1] = __float_as_uint(S[32 + ks2 * 8 + tig + 4][j * 8 + g]);
            mma_tf32(o[j], a, b);
        }
    }
}

__global__ __launch_bounds__(128)
void attn_mma_kernel(const float* __restrict__ pm) {
    int qt  = blockIdx.x;   // 0..7
    int h   = blockIdx.y;   // 0..15
    int seg = blockIdx.z;   // 0..31
    int tid = threadIdx.x;
    int w    = tid >> 5;
    int lane = tid & 31;
    int g   = lane >> 2;
    int tig = lane & 3;

    __shared__ float S[64][KP_];        // Q stage, then K(0..31)/V(32..63)
    __shared__ float Ps[4][16][PP_];

    const float* qbase = g_q + (((size_t)seg * H_ + h) * SEG_ + qt * 64) * DH_;
    #pragma unroll
    for (int i = 0; i < 8; i++) {       // 1024 float4
        int idx = tid + i * 128;
        int r = idx >> 4, c = idx & 15;
        *reinterpret_cast<float4*>(&S[r][c * 4]) =
            *reinterpret_cast<const float4*>(qbase + (size_t)r * DH_ + c * 4);
    }
    __syncthreads();

    uint32_t qf[8][4];
    #pragma unroll
    for (int ks = 0; ks < 8; ks++) {
        qf[ks][0] = __float_as_uint(S[w * 16 + g][ks * 8 + tig]);
        qf[ks][1] = __float_as_uint(S[w * 16 + g + 8][ks * 8 + tig]);
        qf[ks][2] = __float_as_uint(S[w * 16 + g][ks * 8 + tig + 4]);
        qf[ks][3] = __float_as_uint(S[w * 16 + g + 8][ks * 8 + tig + 4]);
    }

    float o[8][4];
    #pragma unroll
    for (int j = 0; j < 8; j++)
        o[j][0] = o[j][1] = o[j][2] = o[j][3] = 0.f;
    float m0 = -1e30f, m1 = -1e30f, l0 = 0.f, l1 = 0.f;

    int i0 = qt * 64 + w * 16 + g;
    int i1 = i0 + 8;

    const float* kb  = g_k + (((size_t)seg * H_ + h) * SEG_) * DH_;
    const float* vb  = g_v + (((size_t)seg * H_ + h) * SEG_) * DH_;
    const float* pmk = pm + (size_t)h * P_ * DH_;
    const float* pmv = pm + (size_t)(H_ + h) * P_ * DH_;

    int nseg = 2 * qt + 2;

    for (int ch = 0; ch <= nseg; ch++) {
        __syncthreads();
        if (ch == 0) {
            #pragma unroll
            for (int i = 0; i < 2; i++) {    // 256 f4 K + 256 f4 V
                int idx = tid + i * 128;
                int r = idx >> 4, c = idx & 15;
                *reinterpret_cast<float4*>(&S[r][c * 4]) =
                    *reinterpret_cast<const float4*>(pmk + (size_t)r * DH_ + c * 4);
                *reinterpret_cast<float4*>(&S[32 + r][c * 4]) =
                    *reinterpret_cast<const float4*>(pmv + (size_t)r * DH_ + c * 4);
            }
        } else {
            int kv0 = (ch - 1) * 32;
            #pragma unroll
            for (int i = 0; i < 4; i++) {    // 512 f4 K + 512 f4 V
                int idx = tid + i * 128;
                int r = idx >> 4, c = idx & 15;
                *reinterpret_cast<float4*>(&S[r][c * 4]) =
                    *reinterpret_cast<const float4*>(kb + (size_t)(kv0 + r) * DH_ + c * 4);
                *reinterpret_cast<float4*>(&S[32 + r][c * 4]) =
                    *reinterpret_cast<const float4*>(vb + (size_t)(kv0 + r) * DH_ + c * 4);
            }
        }
        __syncthreads();

        if (ch == 0)
            attn_step<2, true>(S, Ps[w], qf, o, m0, m1, l0, l1, 0, i0, i1, g, tig);
        else
            attn_step<4, false>(S, Ps[w], qf, o, m0, m1, l0, l1, (ch - 1) * 32, i0, i1, g, tig);
    }

    float inv0 = 1.f / l0, inv1 = 1.f / l1;
    size_t r0 = (size_t)(seg * SEG_ + i0) * D_ + h * DH_;
    size_t r1 = (size_t)(seg * SEG_ + i1) * D_ + h * DH_;
    #pragma unroll
    for (int j = 0; j < 8; j++) {
        int col = j * 8 + 2 * tig;
        *reinterpret_cast<float2*>(&g_ao[r0 + col]) =
            make_float2(tf32r(o[j][0] * inv0), tf32r(o[j][1] * inv0));
        *reinterpret_cast<float2*>(&g_ao[r1 + col]) =
            make_float2(tf32r(o[j][2] * inv1), tf32r(o[j][3] * inv1));
    }
}

// ---------------------------------------------------------------------------
extern "C" void kernel_launch(void* const* d_in, const int* in_sizes, int n_in,
                              void* d_out, int out_size) {
    const float* seq    = (const float*)d_in[0];
    const float* w_norm = (const float*)d_in[1];
    const float* Wqkv   = (const float*)d_in[2];
    const float* Wout   = (const float*)d_in[3];
    const float* pm     = (const float*)d_in[4];
    float* out = (float*)d_out;

    float* xn  = nullptr; cudaGetSymbolAddress((void**)&xn,  g_xn);
    float* qkv = nullptr; cudaGetSymbolAddress((void**)&qkv, g_qkv);
    float* ao  = nullptr; cudaGetSymbolAddress((void**)&ao,  g_ao);
    float* wq  = nullptr; cudaGetSymbolAddress((void**)&wq,  g_wq);
    float* wo  = nullptr; cudaGetSymbolAddress((void**)&wo,  g_wo);

    precompute_kernel<<<1, 32>>>();
    cvt_tf32_kernel<<<(3 * D_ * D_ + 255) / 256, 256>>>(Wqkv, wq, 3 * D_ * D_);
    cvt_tf32_kernel<<<(D_ * D_ + 255) / 256, 256>>>(Wout, wo, D_ * D_);
    rmsnorm_kernel<<<ROWS_, 256>>>(seq, w_norm);
    {
        dim3 grid(3072 / 128, ROWS_ / 128);
        tf32_gemm_kernel<<<grid, 256>>>(xn, wq, qkv, ROWS_, 3072, 1024);
    }
    {
        int total = ROWS_ * H_ * 32;
        rope_split_kernel<<<(total + 255) / 256, 256>>>();
    }
    {
        dim3 grid(8, H_, 32);
        attn_mma_kernel<<<grid, 128>>>(pm);
    }
    {
        dim3 grid(1024 / 128, ROWS_ / 128);
        tf32_gemm_kernel<<<grid, 256>>>(ao, wo, out, ROWS_, 1024, 1024);
    }
}